// round 17
// baseline (speedup 1.0000x reference)
#include <cuda_runtime.h>
#include <cuda_bf16.h>
#include <math.h>
#include <cstdint>
#include <stdint.h>

// Problem constants
#define L_    32768
#define C_    512
#define H_    8
#define D_    64
#define E_    1048576
#define HID_  1024
#define QKV3  1536

typedef __nv_bfloat16 bf16_t;

// ---------------------------------------------------------------------------
// Scratch (device globals; no allocation allowed)
// ---------------------------------------------------------------------------
__device__ bf16_t g_zb[(size_t)L_ * C_];      // LN output (bf16, reused)
__device__ bf16_t g_qkv[(size_t)L_ * QKV3];   // fused q|k|v rows (bf16)
__device__ bf16_t g_attb[(size_t)L_ * C_];    // attention output (bf16)
__device__ bf16_t g_hb[(size_t)L_ * HID_];    // MLP hidden (bf16)
__device__ bf16_t g_wqkv[QKV3 * C_];          // fused Wqkv^T [1536][512]
__device__ bf16_t g_wo[C_ * C_];
__device__ bf16_t g_w1[C_ * HID_];            // W1^T  [HID][C]
__device__ bf16_t g_w2[C_ * HID_];            // W2^T  [C][HID]
__device__ float  g_bqkv[QKV3];               // fused bias
__device__ int    g_seg[L_ + 1];

// ---------------------------------------------------------------------------
// Fused setup kernel (weights transpose+cast, bias concat, segment scan)
// ---------------------------------------------------------------------------
__device__ __forceinline__ void wt_tile(
    const float* __restrict__ W, bf16_t* __restrict__ Wt,
    int K, int N, int n0, int k0, int tx, int ty, float (*t)[33])
{
    #pragma unroll
    for (int i = 0; i < 32; i += 8)
        t[ty + i][tx] = W[(size_t)(k0 + ty + i) * N + n0 + tx];
    __syncthreads();
    #pragma unroll
    for (int i = 0; i < 32; i += 8)
        Wt[(size_t)(n0 + ty + i) * K + k0 + tx] = __float2bfloat16_rn(t[tx][ty + i]);
}

__global__ __launch_bounds__(256) void setup_kernel(
    const float* __restrict__ Wq, const float* __restrict__ Wk,
    const float* __restrict__ Wv, const float* __restrict__ Wo,
    const float* __restrict__ W1, const float* __restrict__ W2,
    const float* __restrict__ bq, const float* __restrict__ bk,
    const float* __restrict__ bv,
    const int* __restrict__ row,
    bf16_t* __restrict__ wqkv, bf16_t* __restrict__ wo,
    bf16_t* __restrict__ w1t, bf16_t* __restrict__ w2t,
    float* __restrict__ bqkv, int* __restrict__ seg)
{
    __shared__ float t[32][33];
    int b = blockIdx.x;
    int tx = threadIdx.x, ty = threadIdx.y;

    if (b < 1024) {
        int job = b >> 8, rem = b & 255;
        int n0 = (rem & 15) * 32, k0 = (rem >> 4) * 32;
        if (job == 3 && rem == 0) {
            int i = ty * 32 + tx;
            for (int base = i; base < C_; base += 256) {
                bqkv[base]          = bq[base];
                bqkv[C_ + base]     = bk[base];
                bqkv[2 * C_ + base] = bv[base];
            }
        }
        const float* W = (job == 0) ? Wq : (job == 1) ? Wk : (job == 2) ? Wv : Wo;
        bf16_t* Wt = (job == 3) ? wo : wqkv + job * C_ * C_;
        wt_tile(W, Wt, C_, C_, n0, k0, tx, ty, t);
    } else if (b < 2048) {
        int idx = b - 1024;
        if (idx < 512) {
            int n0 = (idx & 31) * 32, k0 = (idx >> 5) * 32;
            wt_tile(W1, w1t, C_, HID_, n0, k0, tx, ty, t);
        } else {
            int j = idx - 512;
            int n0 = (j & 15) * 32, k0 = (j >> 4) * 32;
            wt_tile(W2, w2t, HID_, C_, n0, k0, tx, ty, t);
        }
    } else {
        int e = (b - 2048) * 256 + ty * 32 + tx;
        if (e < E_) {
            int r  = row[e];
            int rp = (e == 0) ? -1 : row[e - 1];
            for (int l = rp + 1; l <= r; l++) seg[l] = e;
            if (e == E_ - 1) {
                for (int l = r + 1; l <= L_; l++) seg[l] = E_;
            }
        }
    }
}

// ---------------------------------------------------------------------------
// LayerNorm: one block (128 thr) per row, float4 per thread; bf16 output
// ---------------------------------------------------------------------------
__global__ __launch_bounds__(128) void ln_kernel(
    const float* __restrict__ x, const float* __restrict__ g,
    const float* __restrict__ b, bf16_t* __restrict__ z)
{
    int l = blockIdx.x, tid = threadIdx.x;
    float4 v = ((const float4*)(x + (size_t)l * C_))[tid];
    float s  = v.x + v.y + v.z + v.w;
    float ss = v.x * v.x + v.y * v.y + v.z * v.z + v.w * v.w;
    #pragma unroll
    for (int m = 16; m >= 1; m >>= 1) {
        s  += __shfl_xor_sync(0xffffffffu, s,  m);
        ss += __shfl_xor_sync(0xffffffffu, ss, m);
    }
    __shared__ float sb[4], ssb[4], stat[2];
    int wid = tid >> 5, lane = tid & 31;
    if (lane == 0) { sb[wid] = s; ssb[wid] = ss; }
    __syncthreads();
    if (tid == 0) {
        float S = sb[0] + sb[1] + sb[2] + sb[3];
        float SS = ssb[0] + ssb[1] + ssb[2] + ssb[3];
        float mu  = S * (1.f / 512.f);
        float var = SS * (1.f / 512.f) - mu * mu;
        stat[0] = mu;
        stat[1] = rsqrtf(var + 1e-5f);
    }
    __syncthreads();
    float mu = stat[0], rstd = stat[1];
    float4 gg = ((const float4*)g)[tid];
    float4 bb = ((const float4*)b)[tid];
    float o0 = (v.x - mu) * rstd * gg.x + bb.x;
    float o1 = (v.y - mu) * rstd * gg.y + bb.y;
    float o2 = (v.z - mu) * rstd * gg.z + bb.z;
    float o3 = (v.w - mu) * rstd * gg.w + bb.w;
    __nv_bfloat162 p0 = __floats2bfloat162_rn(o0, o1);
    __nv_bfloat162 p1 = __floats2bfloat162_rn(o2, o3);
    uint2 pk;
    pk.x = *(unsigned*)&p0;
    pk.y = *(unsigned*)&p1;
    ((uint2*)(z + (size_t)l * C_))[tid] = pk;
}

// ---------------------------------------------------------------------------
// Sparse attention: WARP-PER-ROW, single pass, no-max softmax, f32x2 math.
// Per bf16x2 pair: unpack via shl/and (bf16->f32 is a 16-bit shift) and one
// packed fma.rn.f32x2 — replaces 2x cvt + 2x FFMA. IEEE-identical per lane.
// 8 warps/block, grid = L/8. Lane owns 16 contiguous channels
// (head = lane>>2; 4 lanes per head). All bf16 in fused g_qkv rows.
// ---------------------------------------------------------------------------
#define AW 8      // warps (rows) per block
#define ACH 32    // edge chunk (col-index batch via lane regs)

// d(f32x2) += cvt_f32x2(bf16x2 w) * s(f32x2)
#define BF2FMA2(d, w, s) \
    asm("{.reg .b32 lo, hi;\n\t" \
        ".reg .b64 wf;\n\t" \
        "shl.b32 lo, %1, 16;\n\t" \
        "and.b32 hi, %1, 0xFFFF0000;\n\t" \
        "mov.b64 wf, {lo, hi};\n\t" \
        "fma.rn.f32x2 %0, wf, %2, %0;}\n" \
        : "+l"(d) : "r"(w), "l"(s))

__global__ __launch_bounds__(256) void attn_kernel(
    const bf16_t* __restrict__ QKV, const float* __restrict__ bias,
    const int* __restrict__ col, const int* __restrict__ seg,
    bf16_t* __restrict__ out)
{
    int wid = threadIdx.x >> 5, lane = threadIdx.x & 31;
    int l = blockIdx.x * AW + wid;
    int hq = lane >> 2;       // head of this lane

    // ---- q row -> 8 packed f32x2 regs (16 channels/lane), scaled by 0.125
    unsigned long long q2[8];
    {
        const uint4* qp = (const uint4*)(QKV + (size_t)l * QKV3 + lane * 16);
        uint4 a = qp[0], b = qp[1];
        unsigned w[8];
        *(uint4*)&w[0] = a;
        *(uint4*)&w[4] = b;
        #pragma unroll
        for (int j = 0; j < 8; j++) {
            float lo = __uint_as_float(w[j] << 16) * 0.125f;
            float hi = __uint_as_float(w[j] & 0xffff0000u) * 0.125f;
            asm("mov.b64 %0, {%1, %2};" : "=l"(q2[j]) : "f"(lo), "f"(hi));
        }
    }

    unsigned long long acc2[8];
    #pragma unroll
    for (int j = 0; j < 8; j++) acc2[j] = 0ull;
    float rs = 0.f;

    int e0 = seg[l], e1 = seg[l + 1];
    const bf16_t* Kb = QKV + C_ + lane * 16;
    const bf16_t* Vb = QKV + 2 * C_ + lane * 16;
    const float* bp = bias + hq;

    for (int c0 = e0; c0 < e1; c0 += ACH) {
        int cn = min(ACH, e1 - c0);
        int colv = col[c0 + min(lane, cn - 1)];

        for (int i = 0; i < cn; i++) {
            int cx = __shfl_sync(0xffffffffu, colv, i);
            const uint4* kp = (const uint4*)(Kb + (size_t)cx * QKV3);
            const uint4* vp = (const uint4*)(Vb + (size_t)cx * QKV3);
            uint4 ka = kp[0], kb2 = kp[1];
            uint4 va = vp[0], vb2 = vp[1];

            unsigned kw[8];
            *(uint4*)&kw[0] = ka;
            *(uint4*)&kw[4] = kb2;

            // head dot via packed fma (accumulate in f32x2 pair)
            unsigned long long pd2 = 0ull;
            #pragma unroll
            for (int j = 0; j < 8; j++) BF2FMA2(pd2, kw[j], q2[j]);
            float plo, phi;
            asm("mov.b64 {%0, %1}, %2;" : "=f"(plo), "=f"(phi) : "l"(pd2));
            float pd = plo + phi;
            pd += __shfl_xor_sync(0xffffffffu, pd, 1);
            pd += __shfl_xor_sync(0xffffffffu, pd, 2);
            float s = pd + __ldg(bp + (size_t)(c0 + i) * H_);

            // no-max softmax accumulation
            float p = __expf(s);
            rs += p;
            unsigned long long p2;
            asm("mov.b64 %0, {%1, %1};" : "=l"(p2) : "f"(p));

            unsigned vw[8];
            *(uint4*)&vw[0] = va;
            *(uint4*)&vw[4] = vb2;
            #pragma unroll
            for (int j = 0; j < 8; j++) BF2FMA2(acc2[j], vw[j], p2);
        }
    }

    // ---- normalize + write 16 bf16 (two uint4)
    float inv = (rs > 0.f) ? 1.f / rs : 0.f;
    uint4 o[2];
    __nv_bfloat162* o2 = (__nv_bfloat162*)&o[0];
    #pragma unroll
    for (int j = 0; j < 8; j++) {
        float lo, hi;
        asm("mov.b64 {%0, %1}, %2;" : "=f"(lo), "=f"(hi) : "l"(acc2[j]));
        o2[j] = __floats2bfloat162_rn(lo * inv, hi * inv);
    }
    uint4* op = (uint4*)(out + (size_t)l * C_ + lane * 16);
    op[0] = o[0];
    op[1] = o[1];
}

// ---------------------------------------------------------------------------
// BF16 tensor-core GEMM (R10 config): 128x128 tile, warptile 64x32,
// mma.m16n8k16, ldmatrix, BK=32, 4-stage cp.async (wait_group 2), 2 CTAs/SM.
// ---------------------------------------------------------------------------
#define BKP 40
#define STG 4
#define HS_BYTES (2 * STG * 128 * BKP * 2)   // 81920

__device__ __forceinline__ void cp16(uint32_t s, const void* g) {
    asm volatile("cp.async.cg.shared.global [%0], [%1], 16;\n"
                 :: "r"(s), "l"(g));
}

#define LDMX4(r0, r1, r2, r3, addr) \
    asm volatile("ldmatrix.sync.aligned.m8n8.x4.shared.b16 {%0,%1,%2,%3}, [%4];" \
                 : "=r"(r0), "=r"(r1), "=r"(r2), "=r"(r3) : "r"(addr))

template <int EPI, int OBF>
__global__ __launch_bounds__(256, 2) void hgemm_kernel(
    const bf16_t* __restrict__ A, const bf16_t* __restrict__ Bt,
    const float* __restrict__ bias, const float* __restrict__ res,
    void* __restrict__ Cout, int M, int N, int K)
{
    extern __shared__ bf16_t smem[];
    bf16_t* As = smem;
    bf16_t* Bs = smem + STG * 128 * BKP;

    int tid = threadIdx.x;
    int bx = blockIdx.x, by = blockIdx.y;
    int lane = tid & 31, wid = tid >> 5;
    int wm = (wid & 1) * 64, wn = (wid >> 1) * 32;
    int g = lane >> 2, t = lane & 3;

    int srow = tid >> 1;
    int skc  = (tid & 1) * 16;

    const bf16_t* Agp = A  + (size_t)(by * 128 + srow) * K + skc;
    const bf16_t* Bgp = Bt + (size_t)(bx * 128 + srow) * K + skc;
    uint32_t sa = (uint32_t)__cvta_generic_to_shared(As + srow * BKP + skc);
    uint32_t sb = (uint32_t)__cvta_generic_to_shared(Bs + srow * BKP + skc);
    const uint32_t stgb = 128 * BKP * 2;

    uint32_t uA = (uint32_t)__cvta_generic_to_shared(As);
    uint32_t uB = (uint32_t)__cvta_generic_to_shared(Bs);
    int lq = lane >> 3, lr = lane & 7;
    int a_row = (lq & 1) * 8 + lr;
    int a_k   = (lq >> 1) * 8;
    uint32_t a_off[4];
    #pragma unroll
    for (int mi = 0; mi < 4; mi++)
        a_off[mi] = uA + ((wm + mi * 16 + a_row) * BKP + a_k) * 2;
    int b_row = (lq >> 1) * 8 + lr;
    int b_k   = (lq & 1) * 8;
    uint32_t b_off[2];
    #pragma unroll
    for (int p = 0; p < 2; p++)
        b_off[p] = uB + ((wn + p * 16 + b_row) * BKP + b_k) * 2;

    float acc[4][4][4];
    #pragma unroll
    for (int mi = 0; mi < 4; mi++)
        #pragma unroll
        for (int ni = 0; ni < 4; ni++)
            #pragma unroll
            for (int r = 0; r < 4; r++) acc[mi][ni][r] = 0.f;

    int KT = K >> 5;

    #pragma unroll
    for (int s = 0; s < 3; s++) {
        cp16(sa + s * stgb,      Agp + s * 32);
        cp16(sa + s * stgb + 16, Agp + s * 32 + 8);
        cp16(sb + s * stgb,      Bgp + s * 32);
        cp16(sb + s * stgb + 16, Bgp + s * 32 + 8);
        asm volatile("cp.async.commit_group;\n");
    }

    for (int kt = 0; kt < KT; kt++) {
        if (kt < KT - 2)       asm volatile("cp.async.wait_group 2;\n");
        else if (kt == KT - 2) asm volatile("cp.async.wait_group 1;\n");
        else                   asm volatile("cp.async.wait_group 0;\n");
        __syncthreads();

        uint32_t stoff = (kt & (STG - 1)) * stgb;

        #pragma unroll
        for (int ks = 0; ks < 32; ks += 16) {
            unsigned af[4][4];
            unsigned bfr[2][4];
            #pragma unroll
            for (int mi = 0; mi < 4; mi++)
                LDMX4(af[mi][0], af[mi][1], af[mi][2], af[mi][3],
                      a_off[mi] + stoff + ks * 2);
            #pragma unroll
            for (int p = 0; p < 2; p++)
                LDMX4(bfr[p][0], bfr[p][1], bfr[p][2], bfr[p][3],
                      b_off[p] + stoff + ks * 2);
            #pragma unroll
            for (int mi = 0; mi < 4; mi++)
                #pragma unroll
                for (int ni = 0; ni < 4; ni++) {
                    int p = ni >> 1, hh = (ni & 1) * 2;
                    asm volatile(
                        "mma.sync.aligned.m16n8k16.row.col.f32.bf16.bf16.f32 "
                        "{%0,%1,%2,%3}, {%4,%5,%6,%7}, {%8,%9}, {%0,%1,%2,%3};\n"
                        : "+f"(acc[mi][ni][0]), "+f"(acc[mi][ni][1]),
                          "+f"(acc[mi][ni][2]), "+f"(acc[mi][ni][3])
                        : "r"(af[mi][0]), "r"(af[mi][1]),
                          "r"(af[mi][2]), "r"(af[mi][3]),
                          "r"(bfr[p][hh]), "r"(bfr[p][hh + 1]));
                }
        }

        if (kt + 3 < KT) {
            int s = (kt + 3) & (STG - 1);
            cp16(sa + s * stgb,      Agp + (kt + 3) * 32);
            cp16(sa + s * stgb + 16, Agp + (kt + 3) * 32 + 8);
            cp16(sb + s * stgb,      Bgp + (kt + 3) * 32);
            cp16(sb + s * stgb + 16, Bgp + (kt + 3) * 32 + 8);
            asm volatile("cp.async.commit_group;\n");
        }
    }

    #pragma unroll
    for (int mi = 0; mi < 4; mi++) {
        #pragma unroll
        for (int ni = 0; ni < 4; ni++) {
            int col = bx * 128 + wn + ni * 8 + 2 * t;
            float2 bb = *(const float2*)&bias[col];
            #pragma unroll
            for (int h = 0; h < 2; h++) {
                int row = by * 128 + wm + mi * 16 + g + h * 8;
                float v0 = acc[mi][ni][2 * h + 0] + bb.x;
                float v1 = acc[mi][ni][2 * h + 1] + bb.y;
                if (EPI == 1) {
                    v0 = v0 / (1.f + __expf(-v0));
                    v1 = v1 / (1.f + __expf(-v1));
                }
                if (EPI == 2) {
                    float2 rr = *(const float2*)&res[(size_t)row * N + col];
                    v0 += rr.x; v1 += rr.y;
                }
                if (OBF) {
                    *(__nv_bfloat162*)((bf16_t*)Cout + (size_t)row * N + col) =
                        __floats2bfloat162_rn(v0, v1);
                } else {
                    *(float2*)((float*)Cout + (size_t)row * N + col) =
                        make_float2(v0, v1);
                }
            }
        }
    }
}

// ---------------------------------------------------------------------------
// Launch
// ---------------------------------------------------------------------------
extern "C" void kernel_launch(void* const* d_in, const int* in_sizes, int n_in,
                              void* d_out, int out_size)
{
    const float *x, *att_bias, *Wq, *bq, *Wk, *bk, *Wv, *bv, *Wo, *bo;
    const float *ln1g, *ln1b, *ln2g, *ln2b, *W1, *b1, *W2, *b2;
    const int *row, *col;

    if (in_sizes[1] == E_ * H_) {
        x        = (const float*)d_in[0];
        att_bias = (const float*)d_in[1];
        Wq = (const float*)d_in[2];  bq = (const float*)d_in[3];
        Wk = (const float*)d_in[4];  bk = (const float*)d_in[5];
        Wv = (const float*)d_in[6];  bv = (const float*)d_in[7];
        Wo = (const float*)d_in[8];  bo = (const float*)d_in[9];
        ln1g = (const float*)d_in[10]; ln1b = (const float*)d_in[11];
        ln2g = (const float*)d_in[12]; ln2b = (const float*)d_in[13];
        W1 = (const float*)d_in[14]; b1 = (const float*)d_in[15];
        W2 = (const float*)d_in[16]; b2 = (const float*)d_in[17];
        row = (const int*)d_in[18];  col = (const int*)d_in[19];
    } else {
        x   = (const float*)d_in[0];
        row = (const int*)d_in[1];
        col = (const int*)d_in[2];
        att_bias = (const float*)d_in[3];
        Wq = (const float*)d_in[4];  bq = (const float*)d_in[5];
        Wk = (const float*)d_in[6];  bk = (const float*)d_in[7];
        Wv = (const float*)d_in[8];  bv = (const float*)d_in[9];
        Wo = (const float*)d_in[10]; bo = (const float*)d_in[11];
        ln1g = (const float*)d_in[12]; ln1b = (const float*)d_in[13];
        ln2g = (const float*)d_in[14]; ln2b = (const float*)d_in[15];
        W1 = (const float*)d_in[16]; b1 = (const float*)d_in[17];
        W2 = (const float*)d_in[18]; b2 = (const float*)d_in[19];
    }

    bf16_t *pz, *pqkv, *pa, *ph, *pwqkv, *pwo, *pw1, *pw2;
    float *pbqkv;
    int* pseg;
    cudaGetSymbolAddress((void**)&pz,    g_zb);
    cudaGetSymbolAddress((void**)&pqkv,  g_qkv);
    cudaGetSymbolAddress((void**)&pa,    g_attb);
    cudaGetSymbolAddress((void**)&ph,    g_hb);
    cudaGetSymbolAddress((void**)&pwqkv, g_wqkv);
    cudaGetSymbolAddress((void**)&pwo,   g_wo);
    cudaGetSymbolAddress((void**)&pw1,   g_w1);
    cudaGetSymbolAddress((void**)&pw2,   g_w2);
    cudaGetSymbolAddress((void**)&pbqkv, g_bqkv);
    cudaGetSymbolAddress((void**)&pseg,  g_seg);

    static bool attr_done = false;
    if (!attr_done) {
        cudaFuncSetAttribute(hgemm_kernel<0,1>, cudaFuncAttributeMaxDynamicSharedMemorySize, HS_BYTES);
        cudaFuncSetAttribute(hgemm_kernel<2,0>, cudaFuncAttributeMaxDynamicSharedMemorySize, HS_BYTES);
        cudaFuncSetAttribute(hgemm_kernel<1,1>, cudaFuncAttributeMaxDynamicSharedMemorySize, HS_BYTES);
        attr_done = true;
    }

    float* out = (float*)d_out;

    dim3 t32(32, 8);
    // 1. fused setup: weights + bias + segments (one launch)
    setup_kernel<<<6144, t32>>>(Wq, Wk, Wv, Wo, W1, W2, bq, bk, bv, row,
                                pwqkv, pwo, pw1, pw2, pbqkv, pseg);
    // 2. z = LN1(x)  (bf16)
    ln_kernel<<<L_, 128>>>(x, ln1g, ln1b, pz);
    // 3. fused qkv projection
    dim3 gQKV(QKV3 / 128, L_ / 128);
    hgemm_kernel<0, 1><<<gQKV, 256, HS_BYTES>>>(pz, pwqkv, pbqkv, nullptr, pqkv, L_, QKV3, C_);
    // 4. sparse attention (f32x2 inner loop; ncu capture slot)
    attn_kernel<<<L_ / AW, 256>>>(pqkv, att_bias, col, pseg, pa);
    // 5. out = x + att @ Wo + bo
    dim3 gC(C_ / 128, L_ / 128);
    hgemm_kernel<2, 0><<<gC, 256, HS_BYTES>>>(pa, pwo, bo, x, out, L_, C_, C_);
    // 6. z = LN2(out)
    ln_kernel<<<L_, 128>>>(out, ln2g, ln2b, pz);
    // 7. h = silu(z @ W1 + b1)
    dim3 gH(HID_ / 128, L_ / 128);
    hgemm_kernel<1, 1><<<gH, 256, HS_BYTES>>>(pz, pw1, b1, nullptr, ph, L_, HID_, C_);
    // 8. out = out + h @ W2 + b2
    hgemm_kernel<2, 0><<<gC, 256, HS_BYTES>>>(ph, pw2, b2, out, out, L_, C_, HID_);
}